// round 8
// baseline (speedup 1.0000x reference)
#include <cuda_runtime.h>
#include <cuda.h>

// Problem constants
#define BB 32
#define FF 64
#define LL 8192
#define KK 8
#define TT 128          // output steps per chunk
#define WW 128          // warm-up steps (validated rounds 2-7: rel_err ~1e-7)
#define NCH (LL / TT)   // 64 chunks -> 2048 blocks, single wave at 16/SM
#define TILE 16         // steps per TMA-stored tile (box 16 cols x 64 rows, SW64)
#define XS_N (WW + TT + KK)   // 264

#define X_SCALE 20.0f
#define THR 0.25f
#define BETA 15.0f

// SW64 swizzle on byte offsets (matches CU_TENSOR_MAP_SWIZZLE_64B)
__device__ __forceinline__ int sw64(int off) {
    return off ^ ((off >> 3) & 0x30);
}

// Fused conv + LIF scan + logits. Grid (B, NCH), 64 threads (one per filter).
// I/z/s tiles staged in packed SW64 smem layout and stored to global via 2D
// TMA bulk-tensor stores (async proxy -> bypasses L1/LSU entirely).
// s = (z >= 0) derived in registers at staging time.
__global__ void __launch_bounds__(64, 16) snn_tma_kernel(
    const float* __restrict__ x,
    const float* __restrict__ conv_w,
    const float* __restrict__ raw_tau,
    float* __restrict__ out,
    const __grid_constant__ CUtensorMap mapI,
    const __grid_constant__ CUtensorMap mapZ,
    const __grid_constant__ CUtensorMap mapS)
{
    __shared__ __align__(1024) char tI[FF * 64];   // 64 rows x 64B (16 floats)
    __shared__ __align__(1024) char tZ[FF * 64];
    __shared__ __align__(1024) char tS[FF * 64];
    __shared__ float xs[XS_N];
    __shared__ float pm[TILE * 4];                 // 4 groups x 16 cols partial max

    const int b = blockIdx.x;
    const int c = blockIdx.y;
    const int f = threadIdx.x;
    const int t0 = c * TT;
    const int tstart = (c == 0) ? 0 : (t0 - WW);
    const int nwarm = t0 - tstart;    // 0 or WW

    // Unit-norm filter weights (clamp 1e-8)
    float w[KK];
    float nrm = 0.0f;
#pragma unroll
    for (int k = 0; k < KK; k++) {
        w[k] = conv_w[f * KK + k];
        nrm += w[k] * w[k];
    }
    nrm = fmaxf(sqrtf(nrm), 1e-8f);
#pragma unroll
    for (int k = 0; k < KK; k++) w[k] = w[k] / nrm;

    // alpha = exp(-1 / (softplus(raw_tau) + 1e-4))
    const float rt = raw_tau[f];
    const float sp = fmaxf(rt, 0.0f) + log1pf(expf(-fabsf(rt)));
    const float alpha = expf(-1.0f / (sp + 1e-4f));
    const float oma = 1.0f - alpha;

    // Stage pre-scaled x window, zero-padded left. xs[i] = 20*x[b, tstart-7+i]
    const float* xb = x + b * LL;
    const int base = tstart - (KK - 1);
    const int total = nwarm + TT + (KK - 1);
    for (int i = f; i < total; i += FF) {
        const int g = base + i;
        xs[i] = (g >= 0) ? (X_SCALE * xb[g]) : 0.0f;
    }
    __syncthreads();

    // 8-register circular window: win[(p+k)&7] == xs[p+k]
    float win[8];
#pragma unroll
    for (int i = 0; i < 8; i++) win[i] = xs[i];

    float v = 0.0f;

    // ---- warm-up: recurrence only ----
    for (int p = 0; p < nwarm; p += 8) {
#pragma unroll
        for (int u = 0; u < 8; u++) {
            float I = 0.0f;
#pragma unroll
            for (int k = 0; k < KK; k++) I = fmaf(w[k], win[(u + k) & 7], I);
            const float vpre = fmaf(oma, I, alpha * v);
            v = (vpre >= THR) ? 0.0f : vpre;
            win[u] = xs[p + u + 8];
        }
    }

    float* const logits = out + (size_t)3 * BB * FF * LL;
    const int g4 = f >> 4;        // group 0..3 (16 filters each)
    const int cc = f & 15;        // time column 0..15
    const int rowbase = b * FF;

    // ---- main: TILE steps -> packed SW64 smem tiles -> TMA bulk store ----
    for (int jb = 0; jb < TT; jb += TILE) {
#pragma unroll
        for (int q = 0; q < TILE; q += 8) {
            float Ia[8], Za[8];
#pragma unroll
            for (int u = 0; u < 8; u++) {
                float I = 0.0f;
#pragma unroll
                for (int k = 0; k < KK; k++) I = fmaf(w[k], win[(u + k) & 7], I);
                const float vpre = fmaf(oma, I, alpha * v);
                Ia[u] = I;
                Za[u] = fmaf(BETA, vpre, -BETA * THR);
                v = (vpre >= THR) ? 0.0f : vpre;
                win[u] = xs[nwarm + jb + q + u + 8];
            }
            // packed SW64 staging: row f (64B), byte cols q*4 and q*4+16
            const int o0 = f * 64 + q * 4;
            *(float4*)(tI + sw64(o0))      = make_float4(Ia[0], Ia[1], Ia[2], Ia[3]);
            *(float4*)(tI + sw64(o0 + 16)) = make_float4(Ia[4], Ia[5], Ia[6], Ia[7]);
            *(float4*)(tZ + sw64(o0))      = make_float4(Za[0], Za[1], Za[2], Za[3]);
            *(float4*)(tZ + sw64(o0 + 16)) = make_float4(Za[4], Za[5], Za[6], Za[7]);
            *(float4*)(tS + sw64(o0)) = make_float4(
                (Za[0] >= 0.0f) ? 1.0f : 0.0f, (Za[1] >= 0.0f) ? 1.0f : 0.0f,
                (Za[2] >= 0.0f) ? 1.0f : 0.0f, (Za[3] >= 0.0f) ? 1.0f : 0.0f);
            *(float4*)(tS + sw64(o0 + 16)) = make_float4(
                (Za[4] >= 0.0f) ? 1.0f : 0.0f, (Za[5] >= 0.0f) ? 1.0f : 0.0f,
                (Za[6] >= 0.0f) ? 1.0f : 0.0f, (Za[7] >= 0.0f) ? 1.0f : 0.0f);
        }
        __syncthreads();

        const int colbase = t0 + jb;

        // Elected thread: fence generic->async, issue 3 TMA 2D stores.
        if (f == 0) {
            asm volatile("fence.proxy.async;" ::: "memory");
            const unsigned sI = (unsigned)__cvta_generic_to_shared(tI);
            const unsigned sZ = (unsigned)__cvta_generic_to_shared(tZ);
            const unsigned sS = (unsigned)__cvta_generic_to_shared(tS);
            asm volatile("cp.async.bulk.tensor.2d.global.shared::cta.tile.bulk_group [%0, {%1, %2}], [%3];"
                         :: "l"(&mapI), "r"(colbase), "r"(rowbase), "r"(sI) : "memory");
            asm volatile("cp.async.bulk.tensor.2d.global.shared::cta.tile.bulk_group [%0, {%1, %2}], [%3];"
                         :: "l"(&mapZ), "r"(colbase), "r"(rowbase), "r"(sZ) : "memory");
            asm volatile("cp.async.bulk.tensor.2d.global.shared::cta.tile.bulk_group [%0, {%1, %2}], [%3];"
                         :: "l"(&mapS), "r"(colbase), "r"(rowbase), "r"(sS) : "memory");
            asm volatile("cp.async.bulk.commit_group;" ::: "memory");
        }

        // Logits partials (concurrent with TMA engine reads; read-read is safe):
        // group g4 reduces its 16 filters for column cc.
        {
            float m = -3.4e38f;
#pragma unroll
            for (int i = 0; i < 16; i++) {
                const int r = g4 * 16 + i;
                m = fmaxf(m, *(const float*)(tZ + (r * 64 + ((cc * 4) ^ ((r & 6) * 8)))));
            }
            pm[cc * 4 + g4] = m;
        }
        __syncthreads();

        if (f == 0)
            asm volatile("cp.async.bulk.wait_group.read 0;" ::: "memory");
        if (f < TILE) {
            const float4 p4 = *(const float4*)&pm[f * 4];
            logits[b * LL + colbase + f] =
                fmaxf(fmaxf(p4.x, p4.y), fmaxf(p4.z, p4.w));
        }
        __syncthreads();   // tiles + pm free for next iteration
    }

    if (f == 0)
        asm volatile("cp.async.bulk.wait_group 0;" ::: "memory");
}

// Host-side tensormap encode via driver entry point (no -lcuda needed).
typedef CUresult (*PFN_encodeTiled)(
    CUtensorMap*, CUtensorMapDataType, cuuint32_t, void*,
    const cuuint64_t*, const cuuint64_t*, const cuuint32_t*, const cuuint32_t*,
    CUtensorMapInterleave, CUtensorMapSwizzle, CUtensorMapL2promotion,
    CUtensorMapFloatOOBfill);

static void make_map(PFN_encodeTiled enc, CUtensorMap* m, float* basePtr)
{
    cuuint64_t gdim[2]   = {(cuuint64_t)LL, (cuuint64_t)BB * FF};
    cuuint64_t gstride[1] = {(cuuint64_t)LL * sizeof(float)};
    cuuint32_t box[2]    = {TILE, FF};
    cuuint32_t estr[2]   = {1, 1};
    enc(m, CU_TENSOR_MAP_DATA_TYPE_FLOAT32, 2, (void*)basePtr,
        gdim, gstride, box, estr,
        CU_TENSOR_MAP_INTERLEAVE_NONE, CU_TENSOR_MAP_SWIZZLE_64B,
        CU_TENSOR_MAP_L2_PROMOTION_L2_128B, CU_TENSOR_MAP_FLOAT_OOB_FILL_NONE);
}

extern "C" void kernel_launch(void* const* d_in, const int* in_sizes, int n_in,
                              void* d_out, int out_size)
{
    const float* x       = (const float*)d_in[0];
    const float* conv_w  = (const float*)d_in[1];
    const float* raw_tau = (const float*)d_in[2];
    float* out = (float*)d_out;

    void* fp = nullptr;
    cudaDriverEntryPointQueryResult qr;
    cudaGetDriverEntryPointByVersion("cuTensorMapEncodeTiled", &fp, 12000,
                                     cudaEnableDefault, &qr);
    PFN_encodeTiled enc = (PFN_encodeTiled)fp;

    CUtensorMap mI, mZ, mS;
    make_map(enc, &mI, out);
    make_map(enc, &mZ, out + (size_t)BB * FF * LL);
    make_map(enc, &mS, out + (size_t)2 * BB * FF * LL);

    dim3 grid(BB, NCH);
    snn_tma_kernel<<<grid, FF>>>(x, conv_w, raw_tau, out, mI, mZ, mS);
}

// round 9
// speedup vs baseline: 1.0806x; 1.0806x over previous
#include <cuda_runtime.h>

// Problem constants
#define BB 32
#define FF 64
#define LL 8192
#define KK 8
#define TT 128          // output steps per chunk
#define WW 128          // warm-up steps (validated rounds 2-8: rel_err ~8.7e-8)
#define NCH (LL / TT)   // 64 chunks -> 2048 blocks
#define TILE 32         // steps buffered in smem before coalesced write-out
#define TPAD 36         // row stride: conflict-free STS.128 / LDS.128 / logits
#define XS_N (WW + TT + KK)   // 264

#define X_SCALE 20.0f
#define THR 0.25f
#define BETA 15.0f

typedef unsigned long long ull;

__device__ __forceinline__ ull pack2(float lo, float hi) {
    ull r;
    asm("mov.b64 %0, {%1, %2};" : "=l"(r) : "f"(lo), "f"(hi));
    return r;
}
__device__ __forceinline__ void unpk2(float& lo, float& hi, ull a) {
    asm("mov.b64 {%0, %1}, %2;" : "=f"(lo), "=f"(hi) : "l"(a));
}
__device__ __forceinline__ ull mul2(ull a, ull b) {
    ull r;
    asm("mul.rn.f32x2 %0, %1, %2;" : "=l"(r) : "l"(a), "l"(b));
    return r;
}
__device__ __forceinline__ ull fma2(ull a, ull b, ull c) {
    ull r;
    asm("fma.rn.f32x2 %0, %1, %2, %3;" : "=l"(r) : "l"(a), "l"(b), "l"(c));
    return r;
}

// 4-tap packed accumulation over pairs pr[i0..i0+3] with weight pairs wp[0..3]
#define CONV4(acc, wp, pr, i0) do {                 \
    ull _t = mul2(wp[0], pr[i0]);                   \
    _t = fma2(wp[1], pr[(i0) + 1], _t);             \
    _t = fma2(wp[2], pr[(i0) + 2], _t);             \
    _t = fma2(wp[3], pr[(i0) + 3], _t);             \
    acc = _t; } while (0)

// Fused conv + LIF scan + logits. Grid (B, NCH), 64 threads (one per filter).
// Conv uses polyphase FFMA2: even pairs pr[i]=(X[2i],X[2i+1]) straight from
// smem (no packing), broadcast weight pairs we/wo. Per 8 steps: 32 f32x2 ops
// replace 64 FFMA. s derived from z at write-out (s = z>=0).
__global__ __launch_bounds__(64, 11) void snn_fused_kernel(
    const float* __restrict__ x,
    const float* __restrict__ conv_w,
    const float* __restrict__ raw_tau,
    float* __restrict__ out)
{
    __shared__ __align__(16) float xs[XS_N];
    __shared__ float tI[FF * TPAD];
    __shared__ float tZ[FF * TPAD];
    __shared__ float pm[TILE * 2];

    const int b = blockIdx.x;
    const int c = blockIdx.y;
    const int f = threadIdx.x;
    const int t0 = c * TT;
    const int tstart = (c == 0) ? 0 : (t0 - WW);
    const int nwarm = t0 - tstart;    // 0 or WW

    // Unit-norm filter weights (clamp 1e-8), packed polyphase
    float w[KK];
    float nrm = 0.0f;
#pragma unroll
    for (int k = 0; k < KK; k++) {
        w[k] = conv_w[f * KK + k];
        nrm += w[k] * w[k];
    }
    nrm = fmaxf(sqrtf(nrm), 1e-8f);
#pragma unroll
    for (int k = 0; k < KK; k++) w[k] = w[k] / nrm;
    ull we[4], wo[4];
#pragma unroll
    for (int j = 0; j < 4; j++) {
        we[j] = pack2(w[2 * j], w[2 * j]);
        wo[j] = pack2(w[2 * j + 1], w[2 * j + 1]);
    }

    // alpha = exp(-1 / (softplus(raw_tau) + 1e-4))
    const float rt = raw_tau[f];
    const float sp = fmaxf(rt, 0.0f) + log1pf(expf(-fabsf(rt)));
    const float alpha = expf(-1.0f / (sp + 1e-4f));
    const float oma = 1.0f - alpha;

    // Stage pre-scaled x window, zero-padded both ends.
    // xs[i] = 20*x[b, tstart-7+i]; one extra slot so pair loads never read junk.
    const float* xb = x + b * LL;
    const int base = tstart - (KK - 1);
    const int total = nwarm + TT + KK;   // fills 0..nwarm+TT+7 inclusive
    for (int i = f; i < total; i += FF) {
        const int g = base + i;
        xs[i] = (g >= 0 && g < LL) ? (X_SCALE * xb[g]) : 0.0f;
    }
    __syncthreads();

    // Window pairs pr[0..7] cover X[0..15] relative to current step base p.
    ull pr[8];
    {
        const ulonglong2 u0 = *(const ulonglong2*)&xs[0];
        const ulonglong2 u1 = *(const ulonglong2*)&xs[4];
        pr[0] = u0.x; pr[1] = u0.y; pr[2] = u1.x; pr[3] = u1.y;
    }
    // Carried odd-phase: odch = OD[0].hi of the upcoming block
    float odch;
    {
        ull od0;
        CONV4(od0, wo, pr, 0);
        float lo;
        unpk2(lo, odch, od0);
    }

    float v = 0.0f;

    // ---- warm-up: recurrence only ----
#pragma unroll 1
    for (int p = 0; p < nwarm; p += 8) {
        const ulonglong2 u0 = *(const ulonglong2*)&xs[p + 8];
        const ulonglong2 u1 = *(const ulonglong2*)&xs[p + 12];
        pr[4] = u0.x; pr[5] = u0.y; pr[6] = u1.x; pr[7] = u1.y;

        ull EV0, EV2, EV4, EV6, OD2, OD4, OD6, OD8;
        CONV4(EV0, we, pr, 0); CONV4(EV2, we, pr, 1);
        CONV4(EV4, we, pr, 2); CONV4(EV6, we, pr, 3);
        CONV4(OD2, wo, pr, 1); CONV4(OD4, wo, pr, 2);
        CONV4(OD6, wo, pr, 3); CONV4(OD8, wo, pr, 4);

        float e0l, e0h, e2l, e2h, e4l, e4h, e6l, e6h;
        float o2l, o2h, o4l, o4h, o6l, o6h, o8l, o8h;
        unpk2(e0l, e0h, EV0); unpk2(e2l, e2h, EV2);
        unpk2(e4l, e4h, EV4); unpk2(e6l, e6h, EV6);
        unpk2(o2l, o2h, OD2); unpk2(o4l, o4h, OD4);
        unpk2(o6l, o6h, OD6); unpk2(o8l, o8h, OD8);

        float Iv[8];
        Iv[0] = e0l + odch; Iv[1] = e0h + o2l;
        Iv[2] = e2l + o2h;  Iv[3] = e2h + o4l;
        Iv[4] = e4l + o4h;  Iv[5] = e4h + o6l;
        Iv[6] = e6l + o6h;  Iv[7] = e6h + o8l;
        odch = o8h;

#pragma unroll
        for (int u = 0; u < 8; u++) {
            const float vpre = fmaf(oma, Iv[u], alpha * v);
            v = (vpre >= THR) ? 0.0f : vpre;
        }
        pr[0] = pr[4]; pr[1] = pr[5]; pr[2] = pr[6]; pr[3] = pr[7];
    }

    float* const outI = out;
    float* const outZ = out + (size_t)BB * FF * LL;
    float* const outS = out + (size_t)2 * BB * FF * LL;
    float* const logits = out + (size_t)3 * BB * FF * LL;

    const int g2 = f >> 5;        // warp id (filter group of 32)
    const int cc = f & 31;        // time column 0..31

    // ---- main: TILE steps -> smem tiles -> coalesced write-out ----
#pragma unroll 1
    for (int jb = 0; jb < TT; jb += TILE) {
#pragma unroll
        for (int q = 0; q < TILE; q += 8) {
            const int p = nwarm + jb + q;
            const ulonglong2 u0 = *(const ulonglong2*)&xs[p + 8];
            const ulonglong2 u1 = *(const ulonglong2*)&xs[p + 12];
            pr[4] = u0.x; pr[5] = u0.y; pr[6] = u1.x; pr[7] = u1.y;

            ull EV0, EV2, EV4, EV6, OD2, OD4, OD6, OD8;
            CONV4(EV0, we, pr, 0); CONV4(EV2, we, pr, 1);
            CONV4(EV4, we, pr, 2); CONV4(EV6, we, pr, 3);
            CONV4(OD2, wo, pr, 1); CONV4(OD4, wo, pr, 2);
            CONV4(OD6, wo, pr, 3); CONV4(OD8, wo, pr, 4);

            float e0l, e0h, e2l, e2h, e4l, e4h, e6l, e6h;
            float o2l, o2h, o4l, o4h, o6l, o6h, o8l, o8h;
            unpk2(e0l, e0h, EV0); unpk2(e2l, e2h, EV2);
            unpk2(e4l, e4h, EV4); unpk2(e6l, e6h, EV6);
            unpk2(o2l, o2h, OD2); unpk2(o4l, o4h, OD4);
            unpk2(o6l, o6h, OD6); unpk2(o8l, o8h, OD8);

            float Iv[8], Za[8];
            Iv[0] = e0l + odch; Iv[1] = e0h + o2l;
            Iv[2] = e2l + o2h;  Iv[3] = e2h + o4l;
            Iv[4] = e4l + o4h;  Iv[5] = e4h + o6l;
            Iv[6] = e6l + o6h;  Iv[7] = e6h + o8l;
            odch = o8h;

#pragma unroll
            for (int u = 0; u < 8; u++) {
                const float vpre = fmaf(oma, Iv[u], alpha * v);
                Za[u] = fmaf(BETA, vpre, -BETA * THR);
                v = (vpre >= THR) ? 0.0f : vpre;
            }
            pr[0] = pr[4]; pr[1] = pr[5]; pr[2] = pr[6]; pr[3] = pr[7];

            const int off = f * TPAD + q;
            *(float4*)&tI[off]     = make_float4(Iv[0], Iv[1], Iv[2], Iv[3]);
            *(float4*)&tI[off + 4] = make_float4(Iv[4], Iv[5], Iv[6], Iv[7]);
            *(float4*)&tZ[off]     = make_float4(Za[0], Za[1], Za[2], Za[3]);
            *(float4*)&tZ[off + 4] = make_float4(Za[4], Za[5], Za[6], Za[7]);
        }
        __syncthreads();

        const int colbase = t0 + jb;

        // Coalesced write-out: 8 consecutive lanes cover one full 128B row line.
#pragma unroll
        for (int p2 = 0; p2 < 8; p2++) {
            const int idx = p2 * 256 + f * 4;   // linear in 64x32 tile
            const int row = idx >> 5;
            const int col = idx & 31;
            const size_t g = (size_t)(b * FF + row) * LL + colbase + col;
            const int so = row * TPAD + col;
            const float4 i4 = *(const float4*)&tI[so];
            const float4 z4 = *(const float4*)&tZ[so];
            float4 s4;
            s4.x = (z4.x >= 0.0f) ? 1.0f : 0.0f;
            s4.y = (z4.y >= 0.0f) ? 1.0f : 0.0f;
            s4.z = (z4.z >= 0.0f) ? 1.0f : 0.0f;
            s4.w = (z4.w >= 0.0f) ? 1.0f : 0.0f;
            *(float4*)&outI[g] = i4;
            *(float4*)&outZ[g] = z4;
            *(float4*)&outS[g] = s4;
        }

        // Logits partial max: warp g2 reduces its 32 filters for column cc.
        {
            float m = -3.4e38f;
#pragma unroll
            for (int ff2 = 0; ff2 < 32; ff2++)
                m = fmaxf(m, tZ[(g2 * 32 + ff2) * TPAD + cc]);
            pm[cc * 2 + g2] = m;
        }
        __syncthreads();

        // Combine the 2 warp-partials per column; 32 threads, coalesced store.
        if (f < TILE) {
            logits[b * LL + colbase + f] = fmaxf(pm[f * 2], pm[f * 2 + 1]);
        }
    }
}

extern "C" void kernel_launch(void* const* d_in, const int* in_sizes, int n_in,
                              void* d_out, int out_size)
{
    const float* x       = (const float*)d_in[0];
    const float* conv_w  = (const float*)d_in[1];
    const float* raw_tau = (const float*)d_in[2];
    float* out = (float*)d_out;

    dim3 grid(BB, NCH);
    snn_fused_kernel<<<grid, FF>>>(x, conv_w, raw_tau, out);
}